// round 13
// baseline (speedup 1.0000x reference)
#include <cuda_runtime.h>
#include <math.h>
#include <math_constants.h>
#include <stdint.h>

// Problem constants
#define BB 2
#define NN 2048
#define DIMX 768
#define HH 8
#define FF 192
#define LREL 4095            // 2*N - 1
#define QKVW 512             // H * DK

// ---------------- scratch (device globals; no allocation allowed) ----------
__device__ __align__(256) float g_pos[(size_t)LREL * FF];
__device__ __align__(256) float g_relk[(size_t)(LREL + 1) * QKVW]; // +1 pad row (stays 0)
__device__ __align__(256) float g_q[(size_t)BB * NN * QKVW];       // [b][n][h*64+d]
__device__ __align__(256) float g_k[(size_t)BB * NN * QKVW];
__device__ __align__(256) float g_v[(size_t)BB * NN * QKVW];
__device__ __align__(256) float g_o[(size_t)BB * NN * QKVW];

// ---------------- tf32 mma helpers -----------------------------------------
__device__ __forceinline__ uint32_t f2tf(float x) {
    uint32_t r; asm("cvt.rna.tf32.f32 %0, %1;" : "=r"(r) : "f"(x));
    return r;
}
__device__ __forceinline__ float tfv(float x) { return __uint_as_float(f2tf(x)); }
__device__ __forceinline__ void mma8(float* d, const uint32_t* a, const uint32_t* b) {
    asm volatile(
        "mma.sync.aligned.m16n8k8.row.col.f32.tf32.tf32.f32 "
        "{%0,%1,%2,%3},{%4,%5,%6,%7},{%8,%9},{%0,%1,%2,%3};\n"
        : "+f"(d[0]), "+f"(d[1]), "+f"(d[2]), "+f"(d[3])
        : "r"(a[0]), "r"(a[1]), "r"(a[2]), "r"(a[3]), "r"(b[0]), "r"(b[1]));
}
__device__ __forceinline__ void mma8x3(float* d, const uint32_t* ahi, const uint32_t* alo,
                                       const uint32_t* bhi, const uint32_t* blo) {
    mma8(d, ahi, blo);
    mma8(d, alo, bhi);
    mma8(d, ahi, bhi);
}
#define FU(x) __float_as_uint(x)

// ---------------- K1: positional embedding ----------------------------------
__global__ void pos_embed_kernel() {
    int row = blockIdx.x;
    int i = threadIdx.x;
    float dist = (float)(row - (NN - 1));
    float ad = fabsf(dist);

    float half_life = exp2f(3.0f + 8.0f * (float)i / 31.0f);
    float f_exp = exp2f(-ad / half_life);

    float width = exp2f((float)(i + 1)) - 1.0f;
    float f_cm = (width > ad) ? 1.0f : 0.0f;

    float mean = 64.0f * (float)(i + 1);
    float conc = (mean / 32.0f) * (mean / 32.0f);
    float rate = mean / 1024.0f;
    float log_unnorm = (conc - 1.0f) * logf(ad) - rate * ad;
    float log_norm = lgammaf(conc) - conc * logf(rate);
    float prob = expf(log_unnorm - log_norm) + 1e-8f;
    float pmax = prob;
    #pragma unroll
    for (int o = 16; o; o >>= 1) pmax = fmaxf(pmax, __shfl_xor_sync(0xFFFFFFFFu, pmax, o));
    float f_g = prob / pmax;

    float sgn = (dist > 0.0f) ? 1.0f : ((dist < 0.0f) ? -1.0f : 0.0f);

    float* out = g_pos + (size_t)row * FF;
    out[i]       = f_exp;
    out[32 + i]  = f_cm;
    out[64 + i]  = f_g;
    out[96 + i]  = sgn * f_exp;
    out[128 + i] = sgn * f_cm;
    out[160 + i] = sgn * f_g;
}

// ---------------- K2: tf32x3 GEMM v2 (unchanged) ----------------------------
#define GA 516
#define GB 260
#define VAH 0
#define VAL 4128
#define VBH 8256
#define VBL 10336
#define GEMM_SMEM ((10336 + 2080) * 4)
__global__ __launch_bounds__(256) void gemm_tf32(
    const float* __restrict__ A, const float* __restrict__ B0,
    const float* __restrict__ B1, const float* __restrict__ B2,
    const float* __restrict__ bias, float* __restrict__ C0,
    float* __restrict__ C1, float* __restrict__ C2,
    int M, int K, int Nc, int lda, int ldb, int ldc) {
    extern __shared__ float sg[];
    float* sAh = sg + VAH; float* sAl = sg + VAL;
    float* sBh = sg + VBH; float* sBl = sg + VBL;

    const float* B = B0;
    float* C = C0;
    if (blockIdx.z == 1) { B = B1; C = C1; }
    else if (blockIdx.z == 2) { B = B2; C = C2; }

    int tid = threadIdx.x;
    int warp = tid >> 5, lane = tid & 31;
    int g = lane >> 2, tig = lane & 3;
    int mw = (warp >> 1) * 32, nw = (warp & 1) * 32;
    int m0 = blockIdx.y * 128, n0 = blockIdx.x * 64;

    float acc[2][4][4] = {};

    int am = tid & 127, akg0 = tid >> 7;
    int bn = tid & 63,  bkg0 = tid >> 6;

    for (int k0 = 0; k0 < K; k0 += 32) {
        #pragma unroll
        for (int r = 0; r < 4; r++) {
            int kg = akg0 + 2 * r;
            int m = m0 + am;
            float4 v = make_float4(0.f, 0.f, 0.f, 0.f);
            if (m < M) v = *(const float4*)(A + (size_t)m * lda + k0 + kg * 4);
            float h0 = tfv(v.x), h1 = tfv(v.y), h2 = tfv(v.z), h3 = tfv(v.w);
            *(float4*)&sAh[kg * GA + am * 4] = make_float4(h0, h1, h2, h3);
            *(float4*)&sAl[kg * GA + am * 4] =
                make_float4(v.x - h0, v.y - h1, v.z - h2, v.w - h3);
        }
        #pragma unroll
        for (int r = 0; r < 2; r++) {
            int kg = bkg0 + 4 * r;
            const float* bp = B + (size_t)(k0 + kg * 4) * ldb + n0 + bn;
            float x0 = bp[0];
            float x1 = bp[(size_t)ldb];
            float x2 = bp[2 * (size_t)ldb];
            float x3 = bp[3 * (size_t)ldb];
            float h0 = tfv(x0), h1 = tfv(x1), h2 = tfv(x2), h3 = tfv(x3);
            *(float4*)&sBh[kg * GB + bn * 4] = make_float4(h0, h1, h2, h3);
            *(float4*)&sBl[kg * GB + bn * 4] =
                make_float4(x0 - h0, x1 - h1, x2 - h2, x3 - h3);
        }
        __syncthreads();
        #pragma unroll
        for (int kk = 0; kk < 32; kk += 8) {
            int qa = (kk >> 2) * GA, qb2 = (kk >> 2) * GB;
            uint32_t ah[2][4], al[2][4], bhf[4][2], blf[4][2];
            #pragma unroll
            for (int f = 0; f < 2; f++) {
                int ma = (mw + 16 * f + g) * 4 + tig;
                ah[f][0] = FU(sAh[qa + ma]);
                ah[f][1] = FU(sAh[qa + ma + 32]);
                ah[f][2] = FU(sAh[qa + GA + ma]);
                ah[f][3] = FU(sAh[qa + GA + ma + 32]);
                al[f][0] = FU(sAl[qa + ma]);
                al[f][1] = FU(sAl[qa + ma + 32]);
                al[f][2] = FU(sAl[qa + GA + ma]);
                al[f][3] = FU(sAl[qa + GA + ma + 32]);
            }
            #pragma unroll
            for (int j = 0; j < 4; j++) {
                int nb = (nw + 8 * j + g) * 4 + tig;
                bhf[j][0] = FU(sBh[qb2 + nb]);
                bhf[j][1] = FU(sBh[qb2 + GB + nb]);
                blf[j][0] = FU(sBl[qb2 + nb]);
                blf[j][1] = FU(sBl[qb2 + GB + nb]);
            }
            #pragma unroll
            for (int f = 0; f < 2; f++)
                #pragma unroll
                for (int j = 0; j < 4; j++) mma8(acc[f][j], ah[f], bhf[j]);
            #pragma unroll
            for (int f = 0; f < 2; f++)
                #pragma unroll
                for (int j = 0; j < 4; j++) mma8(acc[f][j], ah[f], blf[j]);
            #pragma unroll
            for (int f = 0; f < 2; f++)
                #pragma unroll
                for (int j = 0; j < 4; j++) mma8(acc[f][j], al[f], bhf[j]);
        }
        __syncthreads();
    }

    #pragma unroll
    for (int f = 0; f < 2; f++) {
        #pragma unroll
        for (int j = 0; j < 4; j++) {
            int n = n0 + nw + 8 * j + 2 * tig;
            float b0v = bias ? bias[n] : 0.0f;
            float b1v = bias ? bias[n + 1] : 0.0f;
            int m = m0 + mw + 16 * f + g;
            if (m < M)
                *(float2*)(C + (size_t)m * ldc + n) =
                    make_float2(acc[f][j][0] + b0v, acc[f][j][1] + b1v);
            if (m + 8 < M)
                *(float2*)(C + (size_t)(m + 8) * ldc + n) =
                    make_float2(acc[f][j][2] + b0v, acc[f][j][3] + b1v);
        }
    }
}

// ---------------- K3: fused attention v3 — 512 threads, 4m x 4n warps -------
// Interleaved hi/lo layout for K/band: (k>>2)*GI + POS8(n) + 2*(k&3) (+1 lo)
#define GI 546
#define POS8(n) (8 * (n) + 2 * ((n) >> 2))
#define FRK 0                      // K tile 16*546 = 8736
#define FRB 8736                   // band tile 8736        -> 17472
#define FQL 17472                  // Q lo, k4 A-layout 16*260 = 4160 -> 21632
#define FPP 21632                  // P hi, k4 A-layout 4160 -> 25792
#define FVS 25792                  // V tile k4 B-layout 4160 -> 29952
#define FGB 29952                  // G buf 2*4352 (slot0 doubles as Q temp) -> 38656
#define FCB 38656                  // cb[64]
#define FDB 38720                  // db[2][64]
#define FREDM 38848                // [4][64]
#define FREDS 39104                // [4][64]
#define FSM_TOT 39360              // *4 = 157,440 B
#define GSLOT2 4352

// split-load 64x64 tile (row-major, ld=QKVW) into interleaved hi/lo, 512 thr
__device__ __forceinline__ void ld_split_i(const float* src, float* dst, int tid) {
    int n = tid & 63, dg = tid >> 6;    // dg 0..7
    #pragma unroll
    for (int r = 0; r < 2; r++) {
        int grp = dg + 8 * r;
        float4 v = *(const float4*)(src + (size_t)n * QKVW + grp * 4);
        float h0 = tfv(v.x), h1 = tfv(v.y), h2 = tfv(v.z), h3 = tfv(v.w);
        int base = grp * GI + POS8(n);
        *(float2*)&dst[base + 0] = make_float2(h0, v.x - h0);
        *(float2*)&dst[base + 2] = make_float2(h1, v.y - h1);
        *(float2*)&dst[base + 4] = make_float2(h2, v.z - h2);
        *(float2*)&dst[base + 6] = make_float2(h3, v.w - h3);
    }
}
// V loader: k4 B-operand layout (k = seq row, n = dv), rna-rounded, 512 thr
__device__ __forceinline__ void ld_v(const float* src, float* dv, int tid) {
    int row = tid & 63, dg = tid >> 6;
    #pragma unroll
    for (int r = 0; r < 2; r++) {
        int grp = dg + 8 * r;
        float4 v = *(const float4*)(src + (size_t)row * QKVW + grp * 4);
        int bb = (row >> 2) * 260 + (row & 3);
        dv[bb + (grp * 4 + 0) * 4] = tfv(v.x);
        dv[bb + (grp * 4 + 1) * 4] = tfv(v.y);
        dv[bb + (grp * 4 + 2) * 4] = tfv(v.z);
        dv[bb + (grp * 4 + 3) * 4] = tfv(v.w);
    }
}

__global__ __launch_bounds__(512, 1) void attn_fused(const float* __restrict__ rcb,
                                                     const float* __restrict__ rpb) {
    extern __shared__ float sm[];

    int bhid = blockIdx.y;
    int b = bhid >> 3, h = bhid & 7;
    int i0 = blockIdx.x * 64;
    int tid = threadIdx.x, warp = tid >> 5, lane = tid & 31;
    int g = lane >> 2, tig = lane & 3;
    int mwl = (warp >> 2) * 16;        // 4 m-warps over 64 rows
    int nwl = (warp & 3) * 16;         // 4 n-warps over 64 cols
    int li0 = mwl + g, li1 = li0 + 8;

    const float* qb = g_q + (size_t)b * NN * QKVW + h * 64;
    const float* kb = g_k + (size_t)b * NN * QKVW + h * 64;
    const float* vb = g_v + (size_t)b * NN * QKVW + h * 64;
    int relbase = 1984 - i0;

    // cb/db thread mapping + weights in regs
    int ccol = tid >> 3, csub = tid & 7;
    float w1r[8], w2r[8];
    #pragma unroll
    for (int ddi = 0; ddi < 8; ddi++) {
        int kg = (csub >> 2) + 2 * ddi;
        int d = 4 * kg + (csub & 3);
        w1r[ddi] = rcb[h * 64 + d];
        w2r[ddi] = rpb[h * 64 + d];
    }

    // ---- prologue ----
    // Qraw (scaled) -> FGB slot0 (row-major, stride 68); band chunk0 -> FRB
    {
        int row = tid & 63, dg = tid >> 6;
        float4 v = *(const float4*)(qb + (size_t)(i0 + row) * QKVW + dg * 8);
        float4 v2 = *(const float4*)(qb + (size_t)(i0 + row) * QKVW + dg * 8 + 4);
        *(float4*)&sm[FGB + row * 68 + dg * 8] =
            make_float4(v.x * 0.125f, v.y * 0.125f, v.z * 0.125f, v.w * 0.125f);
        *(float4*)&sm[FGB + row * 68 + dg * 8 + 4] =
            make_float4(v2.x * 0.125f, v2.y * 0.125f, v2.z * 0.125f, v2.w * 0.125f);
    }
    ld_split_i(g_relk + (size_t)relbase * QKVW + h * 64, sm + FRB, tid);
    __syncthreads();   // P1

    // extract Q hi to regs; n-warp 0 writes Q lo to FQL
    uint32_t qh[8][4];
    #pragma unroll
    for (int kkg = 0; kkg < 8; kkg++) {
        int kk = 8 * kkg;
        float a0 = sm[FGB + li0 * 68 + kk + tig];
        float a1 = sm[FGB + li1 * 68 + kk + tig];
        float a2 = sm[FGB + li0 * 68 + kk + tig + 4];
        float a3 = sm[FGB + li1 * 68 + kk + tig + 4];
        float h0 = tfv(a0), h1 = tfv(a1), h2 = tfv(a2), h3 = tfv(a3);
        qh[kkg][0] = FU(h0); qh[kkg][1] = FU(h1); qh[kkg][2] = FU(h2); qh[kkg][3] = FU(h3);
        if ((warp & 3) == 0) {
            sm[FQL + 2 * kkg * 260 + 4 * li0 + tig]       = a0 - h0;
            sm[FQL + 2 * kkg * 260 + 4 * li1 + tig]       = a1 - h1;
            sm[FQL + (2 * kkg + 1) * 260 + 4 * li0 + tig] = a2 - h2;
            sm[FQL + (2 * kkg + 1) * 260 + 4 * li1 + tig] = a3 - h3;
        }
    }
    // db[0] from band chunk0
    {
        float accd = 0.0f;
        #pragma unroll
        for (int ddi = 0; ddi < 8; ddi++) {
            int kg = (csub >> 2) + 2 * ddi;
            float2 bv = *(float2*)&sm[FRB + kg * GI + POS8(ccol) + 2 * (csub & 3)];
            accd = fmaf(w2r[ddi], bv.x + bv.y, accd);
        }
        accd += __shfl_xor_sync(0xFFFFFFFFu, accd, 1);
        accd += __shfl_xor_sync(0xFFFFFFFFu, accd, 2);
        accd += __shfl_xor_sync(0xFFFFFFFFu, accd, 4);
        if (csub == 0) sm[FDB + ccol] = accd;
    }
    __syncthreads();   // P2: FQL + db0 visible; FGB(Qtemp) free

    // G chunk0 -> Gbuf slot 0
    {
        float gacc[2][4] = {};
        #pragma unroll
        for (int kkg = 0; kkg < 8; kkg++) {
            uint32_t al[4];
            al[0] = FU(sm[FQL + 2 * kkg * 260 + 4 * li0 + tig]);
            al[1] = FU(sm[FQL + 2 * kkg * 260 + 4 * li1 + tig]);
            al[2] = FU(sm[FQL + (2 * kkg + 1) * 260 + 4 * li0 + tig]);
            al[3] = FU(sm[FQL + (2 * kkg + 1) * 260 + 4 * li1 + tig]);
            #pragma unroll
            for (int j = 0; j < 2; j++) {
                int nb = POS8(nwl + 8 * j + g) + 2 * tig;
                float2 b0 = *(float2*)&sm[FRB + 2 * kkg * GI + nb];
                float2 b1 = *(float2*)&sm[FRB + (2 * kkg + 1) * GI + nb];
                uint32_t bh2[2] = { FU(b0.x), FU(b1.x) };
                uint32_t bl2[2] = { FU(b0.y), FU(b1.y) };
                mma8x3(gacc[j], qh[kkg], al, bh2, bl2);
            }
        }
        float* Gb = sm + FGB;
        #pragma unroll
        for (int j = 0; j < 2; j++) {
            int c = nwl + 8 * j + 2 * tig;
            *(float2*)&Gb[li0 * 68 + c] = make_float2(gacc[j][0], gacc[j][1]);
            *(float2*)&Gb[li1 * 68 + c] = make_float2(gacc[j][2], gacc[j][3]);
        }
    }

    float oacc[2][4] = {};
    float m0r = -CUDART_INF_F, m1r = -CUDART_INF_F;
    float l0 = 0.0f, l1 = 0.0f;

    for (int t = 0; t < 32; t++) {
        __syncthreads();   // S1
        ld_split_i(kb + (size_t)t * 64 * QKVW, sm + FRK, tid);
        ld_v(vb + (size_t)t * 64 * QKVW, sm + FVS, tid);
        ld_split_i(g_relk + (size_t)(relbase + 64 * (t + 1)) * QKVW + h * 64,
                   sm + FRB, tid);
        __syncthreads();   // S2

        // cb (K) and db[(t+1)&1] (band)
        {
            float accc = 0.0f, accd = 0.0f;
            #pragma unroll
            for (int ddi = 0; ddi < 8; ddi++) {
                int kg = (csub >> 2) + 2 * ddi;
                int off = kg * GI + POS8(ccol) + 2 * (csub & 3);
                float2 kv = *(float2*)&sm[FRK + off];
                float2 bv = *(float2*)&sm[FRB + off];
                accc = fmaf(w1r[ddi], kv.x + kv.y, accc);
                accd = fmaf(w2r[ddi], bv.x + bv.y, accd);
            }
            accc += __shfl_xor_sync(0xFFFFFFFFu, accc, 1);
            accc += __shfl_xor_sync(0xFFFFFFFFu, accc, 2);
            accc += __shfl_xor_sync(0xFFFFFFFFu, accc, 4);
            accd += __shfl_xor_sync(0xFFFFFFFFu, accd, 1);
            accd += __shfl_xor_sync(0xFFFFFFFFu, accd, 2);
            accd += __shfl_xor_sync(0xFFFFFFFFu, accd, 4);
            if (csub == 0) {
                sm[FCB + ccol] = accc;
                sm[FDB + ((t + 1) & 1) * 64 + ccol] = accd;
            }
        }

        // content mma + G mma
        float cacc[2][4] = {};
        float gacc[2][4] = {};
        #pragma unroll
        for (int kkg = 0; kkg < 8; kkg++) {
            uint32_t al[4];
            al[0] = FU(sm[FQL + 2 * kkg * 260 + 4 * li0 + tig]);
            al[1] = FU(sm[FQL + 2 * kkg * 260 + 4 * li1 + tig]);
            al[2] = FU(sm[FQL + (2 * kkg + 1) * 260 + 4 * li0 + tig]);
            al[3] = FU(sm[FQL + (2 * kkg + 1) * 260 + 4 * li1 + tig]);
            #pragma unroll
            for (int j = 0; j < 2; j++) {
                int nb = POS8(nwl + 8 * j + g) + 2 * tig;
                float2 b0 = *(float2*)&sm[FRK + 2 * kkg * GI + nb];
                float2 b1 = *(float2*)&sm[FRK + (2 * kkg + 1) * GI + nb];
                uint32_t bh2[2] = { FU(b0.x), FU(b1.x) };
                uint32_t bl2[2] = { FU(b0.y), FU(b1.y) };
                mma8x3(cacc[j], qh[kkg], al, bh2, bl2);
                float2 c0 = *(float2*)&sm[FRB + 2 * kkg * GI + nb];
                float2 c1 = *(float2*)&sm[FRB + (2 * kkg + 1) * GI + nb];
                uint32_t bh3[2] = { FU(c0.x), FU(c1.x) };
                uint32_t bl3[2] = { FU(c0.y), FU(c1.y) };
                mma8x3(gacc[j], qh[kkg], al, bh3, bl3);
            }
        }
        {
            float* Gb = sm + FGB + ((t + 1) & 1) * GSLOT2;
            #pragma unroll
            for (int j = 0; j < 2; j++) {
                int c = nwl + 8 * j + 2 * tig;
                *(float2*)&Gb[li0 * 68 + c] = make_float2(gacc[j][0], gacc[j][1]);
                *(float2*)&Gb[li1 * 68 + c] = make_float2(gacc[j][2], gacc[j][3]);
            }
        }
        __syncthreads();   // S3

        // gather + biases + rowmax
        const float* G0 = sm + FGB + (t & 1) * GSLOT2;
        const float* G1 = sm + FGB + ((t + 1) & 1) * GSLOT2;
        const float* db0 = sm + FDB + (t & 1) * 64;
        const float* db1 = sm + FDB + ((t + 1) & 1) * 64;
        float s0[4], s1[4];
        float rm0 = -CUDART_INF_F, rm1 = -CUDART_INF_F;
        #pragma unroll
        for (int j = 0; j < 2; j++) {
            #pragma unroll
            for (int e = 0; e < 2; e++) {
                int lj = nwl + 8 * j + 2 * tig + e;
                float cbv = sm[FCB + lj];
                int rl0 = lj - li0 + 63;
                int rl1 = lj - li1 + 63;
                float gv0 = (rl0 < 64) ? (G0[li0 * 68 + rl0] + db0[rl0])
                                       : (G1[li0 * 68 + rl0 - 64] + db1[rl0 - 64]);
                float gv1 = (rl1 < 64) ? (G0[li1 * 68 + rl1] + db0[rl1])
                                       : (G1[li1 * 68 + rl1 - 64] + db1[rl1 - 64]);
                float v0 = cacc[j][e]     + gv0 + cbv;
                float v1 = cacc[j][2 + e] + gv1 + cbv;
                s0[2 * j + e] = v0; s1[2 * j + e] = v1;
                rm0 = fmaxf(rm0, v0); rm1 = fmaxf(rm1, v1);
            }
        }
        rm0 = fmaxf(rm0, __shfl_xor_sync(0xFFFFFFFFu, rm0, 1));
        rm0 = fmaxf(rm0, __shfl_xor_sync(0xFFFFFFFFu, rm0, 2));
        rm1 = fmaxf(rm1, __shfl_xor_sync(0xFFFFFFFFu, rm1, 1));
        rm1 = fmaxf(rm1, __shfl_xor_sync(0xFFFFFFFFu, rm1, 2));
        if (tig == 0) {
            sm[FREDM + (warp & 3) * 64 + li0] = rm0;
            sm[FREDM + (warp & 3) * 64 + li1] = rm1;
        }
        __syncthreads();   // S4

        float mn0 = fmaxf(fmaxf(sm[FREDM + li0], sm[FREDM + 64 + li0]),
                          fmaxf(sm[FREDM + 128 + li0], sm[FREDM + 192 + li0]));
        float mn1 = fmaxf(fmaxf(sm[FREDM + li1], sm[FREDM + 64 + li1]),
                          fmaxf(sm[FREDM + 128 + li1], sm[FREDM + 192 + li1]));
        mn0 = fmaxf(m0r, mn0); mn1 = fmaxf(m1r, mn1);
        float sc0 = __expf(m0r - mn0), sc1 = __expf(m1r - mn1);
        m0r = mn0; m1r = mn1;
        float rs0 = 0.0f, rs1 = 0.0f;
        #pragma unroll
        for (int j = 0; j < 2; j++) {
            oacc[j][0] *= sc0; oacc[j][1] *= sc0;
            oacc[j][2] *= sc1; oacc[j][3] *= sc1;
            float p0a = __expf(s0[2 * j] - mn0), p0b = __expf(s0[2 * j + 1] - mn0);
            float p1a = __expf(s1[2 * j] - mn1), p1b = __expf(s1[2 * j + 1] - mn1);
            rs0 += p0a + p0b; rs1 += p1a + p1b;
            int c = nwl + 8 * j + 2 * tig;
            int pb = FPP + (c >> 2) * 260 + (c & 3);
            *(float2*)&sm[pb + 4 * li0] = make_float2(tfv(p0a), tfv(p0b));
            *(float2*)&sm[pb + 4 * li1] = make_float2(tfv(p1a), tfv(p1b));
        }
        rs0 += __shfl_xor_sync(0xFFFFFFFFu, rs0, 1);
        rs0 += __shfl_xor_sync(0xFFFFFFFFu, rs0, 2);
        rs1 += __shfl_xor_sync(0xFFFFFFFFu, rs1, 1);
        rs1 += __shfl_xor_sync(0xFFFFFFFFu, rs1, 2);
        if (tig == 0) {
            sm[FREDS + (warp & 3) * 64 + li0] = rs0;
            sm[FREDS + (warp & 3) * 64 + li1] = rs1;
        }
        __syncthreads();   // S5

        l0 = l0 * sc0 + sm[FREDS + li0] + sm[FREDS + 64 + li0]
                      + sm[FREDS + 128 + li0] + sm[FREDS + 192 + li0];
        l1 = l1 * sc1 + sm[FREDS + li1] + sm[FREDS + 64 + li1]
                      + sm[FREDS + 128 + li1] + sm[FREDS + 192 + li1];

        // PV mma: oacc += P x V  (P hi-only x1, V rna)
        #pragma unroll
        for (int kkg = 0; kkg < 8; kkg++) {
            uint32_t ph[4];
            ph[0] = FU(sm[FPP + 2 * kkg * 260 + 4 * li0 + tig]);
            ph[1] = FU(sm[FPP + 2 * kkg * 260 + 4 * li1 + tig]);
            ph[2] = FU(sm[FPP + (2 * kkg + 1) * 260 + 4 * li0 + tig]);
            ph[3] = FU(sm[FPP + (2 * kkg + 1) * 260 + 4 * li1 + tig]);
            #pragma unroll
            for (int j = 0; j < 2; j++) {
                int n = nwl + 8 * j + g;
                uint32_t bf[2] = { FU(sm[FVS + 2 * kkg * 260 + 4 * n + tig]),
                                   FU(sm[FVS + (2 * kkg + 1) * 260 + 4 * n + tig]) };
                mma8(oacc[j], ph, bf);
            }
        }
    }

    float inv0 = 1.0f / l0, inv1 = 1.0f / l1;
    float* ob = g_o + (size_t)(b * NN + i0) * QKVW + h * 64;
    #pragma unroll
    for (int j = 0; j < 2; j++) {
        int c = nwl + 8 * j + 2 * tig;
        *(float2*)(ob + (size_t)li0 * QKVW + c) =
            make_float2(oacc[j][0] * inv0, oacc[j][1] * inv0);
        *(float2*)(ob + (size_t)li1 * QKVW + c) =
            make_float2(oacc[j][2] * inv1, oacc[j][3] * inv1);
    }
}

// ---------------- launch ----------------------------------------------------
static float* sym_addr(const void* sym) {
    void* p = nullptr;
    cudaGetSymbolAddress(&p, sym);
    return (float*)p;
}

extern "C" void kernel_launch(void* const* d_in, const int* in_sizes, int n_in,
                              void* d_out, int out_size) {
    const float* x    = (const float*)d_in[0];
    const float* Wq   = (const float*)d_in[1];
    const float* Wk   = (const float*)d_in[2];
    const float* Wv   = (const float*)d_in[3];
    const float* Wrel = (const float*)d_in[4];
    const float* Wout = (const float*)d_in[5];
    const float* bout = (const float*)d_in[6];
    const float* rcb  = (const float*)d_in[7];
    const float* rpb  = (const float*)d_in[8];
    float* out = (float*)d_out;

    float* p_pos  = sym_addr(g_pos);
    float* p_relk = sym_addr(g_relk);
    float* p_q    = sym_addr(g_q);
    float* p_k    = sym_addr(g_k);
    float* p_v    = sym_addr(g_v);
    float* p_o    = sym_addr(g_o);

    cudaFuncSetAttribute(gemm_tf32, cudaFuncAttributeMaxDynamicSharedMemorySize,
                         GEMM_SMEM);
    const int FUSED_SMEM = FSM_TOT * 4;   // 157,440 B
    cudaFuncSetAttribute(attn_fused, cudaFuncAttributeMaxDynamicSharedMemorySize,
                         FUSED_SMEM);

    // 1. positional embedding
    pos_embed_kernel<<<LREL, 32>>>();

    // 2. rel_k = pos @ Wrel  (row 4095 of g_relk stays 0 = pad)
    gemm_tf32<<<dim3(QKVW / 64, 32, 1), 256, GEMM_SMEM>>>(
        p_pos, Wrel, nullptr, nullptr, nullptr, p_relk, nullptr, nullptr,
        LREL, FF, QKVW, FF, QKVW, QKVW);

    // 3. q,k,v projections fused into one launch
    gemm_tf32<<<dim3(QKVW / 64, (BB * NN) / 128, 3), 256, GEMM_SMEM>>>(
        x, Wq, Wk, Wv, nullptr, p_q, p_k, p_v,
        BB * NN, DIMX, QKVW, DIMX, QKVW, QKVW);

    // 4. fused logits + online softmax + P@V  (512 threads)
    attn_fused<<<dim3(NN / 64, BB * HH), 512, FUSED_SMEM>>>(rcb, rpb);

    // 5. out = O @ Wout + b_out
    gemm_tf32<<<dim3(DIMX / 64, (BB * NN) / 128, 1), 256, GEMM_SMEM>>>(
        p_o, Wout, nullptr, nullptr, bout, out, nullptr, nullptr,
        BB * NN, QKVW, DIMX, QKVW, DIMX, DIMX);
}

// round 14
// speedup vs baseline: 1.0543x; 1.0543x over previous
#include <cuda_runtime.h>
#include <math.h>
#include <math_constants.h>
#include <stdint.h>

// Problem constants
#define BB 2
#define NN 2048
#define DIMX 768
#define HH 8
#define FF 192
#define LREL 4095            // 2*N - 1
#define QKVW 512             // H * DK

// ---------------- scratch (device globals; no allocation allowed) ----------
__device__ __align__(256) float g_pos[(size_t)LREL * FF];
__device__ __align__(256) float g_relk[(size_t)(LREL + 1) * QKVW]; // +1 pad row (stays 0)
__device__ __align__(256) float g_q[(size_t)BB * NN * QKVW];       // [b][n][h*64+d]
__device__ __align__(256) float g_k[(size_t)BB * NN * QKVW];
__device__ __align__(256) float g_v[(size_t)BB * NN * QKVW];
__device__ __align__(256) float g_o[(size_t)BB * NN * QKVW];

// ---------------- tf32 mma helpers -----------------------------------------
__device__ __forceinline__ uint32_t f2tf(float x) {
    uint32_t r; asm("cvt.rna.tf32.f32 %0, %1;" : "=r"(r) : "f"(x));
    return r;
}
__device__ __forceinline__ float tfv(float x) { return __uint_as_float(f2tf(x)); }
__device__ __forceinline__ void mma8(float* d, const uint32_t* a, const uint32_t* b) {
    asm volatile(
        "mma.sync.aligned.m16n8k8.row.col.f32.tf32.tf32.f32 "
        "{%0,%1,%2,%3},{%4,%5,%6,%7},{%8,%9},{%0,%1,%2,%3};\n"
        : "+f"(d[0]), "+f"(d[1]), "+f"(d[2]), "+f"(d[3])
        : "r"(a[0]), "r"(a[1]), "r"(a[2]), "r"(a[3]), "r"(b[0]), "r"(b[1]));
}
__device__ __forceinline__ void mma8x3(float* d, const uint32_t* ahi, const uint32_t* alo,
                                       const uint32_t* bhi, const uint32_t* blo) {
    mma8(d, ahi, blo);
    mma8(d, alo, bhi);
    mma8(d, ahi, bhi);
}
#define FU(x) __float_as_uint(x)

// ---------------- K1: positional embedding ----------------------------------
__global__ void pos_embed_kernel() {
    int row = blockIdx.x;
    int i = threadIdx.x;
    float dist = (float)(row - (NN - 1));
    float ad = fabsf(dist);

    float half_life = exp2f(3.0f + 8.0f * (float)i / 31.0f);
    float f_exp = exp2f(-ad / half_life);

    float width = exp2f((float)(i + 1)) - 1.0f;
    float f_cm = (width > ad) ? 1.0f : 0.0f;

    float mean = 64.0f * (float)(i + 1);
    float conc = (mean / 32.0f) * (mean / 32.0f);
    float rate = mean / 1024.0f;
    float log_unnorm = (conc - 1.0f) * logf(ad) - rate * ad;
    float log_norm = lgammaf(conc) - conc * logf(rate);
    float prob = expf(log_unnorm - log_norm) + 1e-8f;
    float pmax = prob;
    #pragma unroll
    for (int o = 16; o; o >>= 1) pmax = fmaxf(pmax, __shfl_xor_sync(0xFFFFFFFFu, pmax, o));
    float f_g = prob / pmax;

    float sgn = (dist > 0.0f) ? 1.0f : ((dist < 0.0f) ? -1.0f : 0.0f);

    float* out = g_pos + (size_t)row * FF;
    out[i]       = f_exp;
    out[32 + i]  = f_cm;
    out[64 + i]  = f_g;
    out[96 + i]  = sgn * f_exp;
    out[128 + i] = sgn * f_cm;
    out[160 + i] = sgn * f_g;
}

// ---------------- K2: tf32x3 GEMM v2 (unchanged) ----------------------------
#define GA 516
#define GB 260
#define VAH 0
#define VAL 4128
#define VBH 8256
#define VBL 10336
#define GEMM_SMEM ((10336 + 2080) * 4)
__global__ __launch_bounds__(256) void gemm_tf32(
    const float* __restrict__ A, const float* __restrict__ B0,
    const float* __restrict__ B1, const float* __restrict__ B2,
    const float* __restrict__ bias, float* __restrict__ C0,
    float* __restrict__ C1, float* __restrict__ C2,
    int M, int K, int Nc, int lda, int ldb, int ldc) {
    extern __shared__ float sg[];
    float* sAh = sg + VAH; float* sAl = sg + VAL;
    float* sBh = sg + VBH; float* sBl = sg + VBL;

    const float* B = B0;
    float* C = C0;
    if (blockIdx.z == 1) { B = B1; C = C1; }
    else if (blockIdx.z == 2) { B = B2; C = C2; }

    int tid = threadIdx.x;
    int warp = tid >> 5, lane = tid & 31;
    int g = lane >> 2, tig = lane & 3;
    int mw = (warp >> 1) * 32, nw = (warp & 1) * 32;
    int m0 = blockIdx.y * 128, n0 = blockIdx.x * 64;

    float acc[2][4][4] = {};

    int am = tid & 127, akg0 = tid >> 7;
    int bn = tid & 63,  bkg0 = tid >> 6;

    for (int k0 = 0; k0 < K; k0 += 32) {
        #pragma unroll
        for (int r = 0; r < 4; r++) {
            int kg = akg0 + 2 * r;
            int m = m0 + am;
            float4 v = make_float4(0.f, 0.f, 0.f, 0.f);
            if (m < M) v = *(const float4*)(A + (size_t)m * lda + k0 + kg * 4);
            float h0 = tfv(v.x), h1 = tfv(v.y), h2 = tfv(v.z), h3 = tfv(v.w);
            *(float4*)&sAh[kg * GA + am * 4] = make_float4(h0, h1, h2, h3);
            *(float4*)&sAl[kg * GA + am * 4] =
                make_float4(v.x - h0, v.y - h1, v.z - h2, v.w - h3);
        }
        #pragma unroll
        for (int r = 0; r < 2; r++) {
            int kg = bkg0 + 4 * r;
            const float* bp = B + (size_t)(k0 + kg * 4) * ldb + n0 + bn;
            float x0 = bp[0];
            float x1 = bp[(size_t)ldb];
            float x2 = bp[2 * (size_t)ldb];
            float x3 = bp[3 * (size_t)ldb];
            float h0 = tfv(x0), h1 = tfv(x1), h2 = tfv(x2), h3 = tfv(x3);
            *(float4*)&sBh[kg * GB + bn * 4] = make_float4(h0, h1, h2, h3);
            *(float4*)&sBl[kg * GB + bn * 4] =
                make_float4(x0 - h0, x1 - h1, x2 - h2, x3 - h3);
        }
        __syncthreads();
        #pragma unroll
        for (int kk = 0; kk < 32; kk += 8) {
            int qa = (kk >> 2) * GA, qb2 = (kk >> 2) * GB;
            uint32_t ah[2][4], al[2][4], bhf[4][2], blf[4][2];
            #pragma unroll
            for (int f = 0; f < 2; f++) {
                int ma = (mw + 16 * f + g) * 4 + tig;
                ah[f][0] = FU(sAh[qa + ma]);
                ah[f][1] = FU(sAh[qa + ma + 32]);
                ah[f][2] = FU(sAh[qa + GA + ma]);
                ah[f][3] = FU(sAh[qa + GA + ma + 32]);
                al[f][0] = FU(sAl[qa + ma]);
                al[f][1] = FU(sAl[qa + ma + 32]);
                al[f][2] = FU(sAl[qa + GA + ma]);
                al[f][3] = FU(sAl[qa + GA + ma + 32]);
            }
            #pragma unroll
            for (int j = 0; j < 4; j++) {
                int nb = (nw + 8 * j + g) * 4 + tig;
                bhf[j][0] = FU(sBh[qb2 + nb]);
                bhf[j][1] = FU(sBh[qb2 + GB + nb]);
                blf[j][0] = FU(sBl[qb2 + nb]);
                blf[j][1] = FU(sBl[qb2 + GB + nb]);
            }
            #pragma unroll
            for (int f = 0; f < 2; f++)
                #pragma unroll
                for (int j = 0; j < 4; j++) mma8(acc[f][j], ah[f], bhf[j]);
            #pragma unroll
            for (int f = 0; f < 2; f++)
                #pragma unroll
                for (int j = 0; j < 4; j++) mma8(acc[f][j], ah[f], blf[j]);
            #pragma unroll
            for (int f = 0; f < 2; f++)
                #pragma unroll
                for (int j = 0; j < 4; j++) mma8(acc[f][j], al[f], bhf[j]);
        }
        __syncthreads();
    }

    #pragma unroll
    for (int f = 0; f < 2; f++) {
        #pragma unroll
        for (int j = 0; j < 4; j++) {
            int n = n0 + nw + 8 * j + 2 * tig;
            float b0v = bias ? bias[n] : 0.0f;
            float b1v = bias ? bias[n + 1] : 0.0f;
            int m = m0 + mw + 16 * f + g;
            if (m < M)
                *(float2*)(C + (size_t)m * ldc + n) =
                    make_float2(acc[f][j][0] + b0v, acc[f][j][1] + b1v);
            if (m + 8 < M)
                *(float2*)(C + (size_t)(m + 8) * ldc + n) =
                    make_float2(acc[f][j][2] + b0v, acc[f][j][3] + b1v);
        }
    }
}

// ---------------- K3: fused attention v4 — 256 thr, PV x1, V dbl-buf --------
// Interleaved hi/lo layout for K/band: (k>>2)*GI + POS8(n) + 2*(k&3) (+1 lo)
#define GI 546
#define POS8(n) (8 * (n) + 2 * ((n) >> 2))
#define FRK 0                      // K tile 16*546 = 8736
#define FRB 8736                   // band tile 8736      -> 17472
#define FPP 17472                  // P hi, k4 A-layout 4160 -> 21632
#define FVS 21632                  // V, 2 slots x 4160 = 8320 -> 29952
#define FGB 29952                  // G buf 2*4352 (slot0 doubles as Q temp) -> 38656
#define FCB 38656                  // cb[64]
#define FDB 38720                  // db[2][64]
#define FREDM 38848                // [2][64]
#define FREDS 38976                // [2][64]
#define FSM_TOT 39104              // *4 = 156,416 B
#define GSLOT2 4352
#define VSLOT 4160

// split-load 64x64 tile (row-major, ld=QKVW) into interleaved hi/lo, 256 thr
__device__ __forceinline__ void ld_split_i(const float* src, float* dst, int tid) {
    int n = tid & 63, dg = tid >> 6;    // dg 0..3
    #pragma unroll
    for (int r = 0; r < 4; r++) {
        int grp = dg + 4 * r;
        float4 v = *(const float4*)(src + (size_t)n * QKVW + grp * 4);
        float h0 = tfv(v.x), h1 = tfv(v.y), h2 = tfv(v.z), h3 = tfv(v.w);
        int base = grp * GI + POS8(n);
        *(float2*)&dst[base + 0] = make_float2(h0, v.x - h0);
        *(float2*)&dst[base + 2] = make_float2(h1, v.y - h1);
        *(float2*)&dst[base + 4] = make_float2(h2, v.z - h2);
        *(float2*)&dst[base + 6] = make_float2(h3, v.w - h3);
    }
}
// V loader: k4 B-operand layout (k = seq row, n = dv), rna-rounded, 256 thr
__device__ __forceinline__ void ld_v(const float* src, float* dv, int tid) {
    int row = tid & 63, dg = tid >> 6;
    #pragma unroll
    for (int r = 0; r < 4; r++) {
        int grp = dg + 4 * r;
        float4 v = *(const float4*)(src + (size_t)row * QKVW + grp * 4);
        int bb = (row >> 2) * 260 + (row & 3);
        dv[bb + (grp * 4 + 0) * 4] = tfv(v.x);
        dv[bb + (grp * 4 + 1) * 4] = tfv(v.y);
        dv[bb + (grp * 4 + 2) * 4] = tfv(v.z);
        dv[bb + (grp * 4 + 3) * 4] = tfv(v.w);
    }
}

__global__ __launch_bounds__(256, 1) void attn_fused(const float* __restrict__ rcb,
                                                     const float* __restrict__ rpb) {
    extern __shared__ float sm[];

    int bhid = blockIdx.y;
    int b = bhid >> 3, h = bhid & 7;
    int i0 = blockIdx.x * 64;
    int tid = threadIdx.x, warp = tid >> 5, lane = tid & 31;
    int g = lane >> 2, tig = lane & 3;
    int mwl = (warp >> 1) * 16, nwl = (warp & 1) * 32;
    int li0 = mwl + g, li1 = li0 + 8;

    const float* qb = g_q + (size_t)b * NN * QKVW + h * 64;
    const float* kb = g_k + (size_t)b * NN * QKVW + h * 64;
    const float* vb = g_v + (size_t)b * NN * QKVW + h * 64;
    int relbase = 1984 - i0;

    // ---- prologue: Qraw (scaled) -> FGB slot0 temp; band chunk0 -> FRB ----
    {
        int row = tid & 63, dg = tid >> 6;
        #pragma unroll
        for (int r = 0; r < 4; r++) {
            int grp = dg + 4 * r;
            float4 v = *(const float4*)(qb + (size_t)(i0 + row) * QKVW + grp * 4);
            *(float4*)&sm[FGB + row * 68 + grp * 4] =
                make_float4(v.x * 0.125f, v.y * 0.125f, v.z * 0.125f, v.w * 0.125f);
        }
    }
    ld_split_i(g_relk + (size_t)relbase * QKVW + h * 64, sm + FRB, tid);
    __syncthreads();   // P1

    // extract Q fragments to registers (hi/lo)
    uint32_t qh[8][4], ql[8][4];
    #pragma unroll
    for (int kkg = 0; kkg < 8; kkg++) {
        int kk = 8 * kkg;
        float a0 = sm[FGB + li0 * 68 + kk + tig];
        float a1 = sm[FGB + li1 * 68 + kk + tig];
        float a2 = sm[FGB + li0 * 68 + kk + tig + 4];
        float a3 = sm[FGB + li1 * 68 + kk + tig + 4];
        float h0 = tfv(a0), h1 = tfv(a1), h2 = tfv(a2), h3 = tfv(a3);
        qh[kkg][0] = FU(h0); qh[kkg][1] = FU(h1); qh[kkg][2] = FU(h2); qh[kkg][3] = FU(h3);
        ql[kkg][0] = FU(tfv(a0 - h0)); ql[kkg][1] = FU(tfv(a1 - h1));
        ql[kkg][2] = FU(tfv(a2 - h2)); ql[kkg][3] = FU(tfv(a3 - h3));
    }

    // db[0] from band chunk0
    {
        int col = tid >> 2;
        float accd = 0.0f;
        #pragma unroll
        for (int dd = 0; dd < 16; dd++) {
            int d = (tid & 3) + 4 * dd;
            float2 bv = *(float2*)&sm[FRB + dd * GI + POS8(col) + 2 * (tid & 3)];
            accd = fmaf(rpb[h * 64 + d], bv.x + bv.y, accd);
        }
        accd += __shfl_xor_sync(0xFFFFFFFFu, accd, 1);
        accd += __shfl_xor_sync(0xFFFFFFFFu, accd, 2);
        if ((tid & 3) == 0) sm[FDB + col] = accd;
    }
    __syncthreads();   // P2: Q regs extracted; FGB temp free

    // G chunk0 -> Gbuf slot 0
    {
        float gacc[4][4] = {};
        #pragma unroll
        for (int kkg = 0; kkg < 8; kkg++) {
            int g0 = (2 * kkg) * GI, g1 = g0 + GI;
            #pragma unroll
            for (int j = 0; j < 4; j++) {
                int nb = POS8(nwl + 8 * j + g) + 2 * tig;
                float2 b0 = *(float2*)&sm[FRB + g0 + nb];
                float2 b1 = *(float2*)&sm[FRB + g1 + nb];
                uint32_t bh2[2] = { FU(b0.x), FU(b1.x) };
                uint32_t bl2[2] = { FU(b0.y), FU(b1.y) };
                mma8x3(gacc[j], qh[kkg], ql[kkg], bh2, bl2);
            }
        }
        float* Gb = sm + FGB;
        #pragma unroll
        for (int j = 0; j < 4; j++) {
            int c = nwl + 8 * j + 2 * tig;
            *(float2*)&Gb[li0 * 68 + c] = make_float2(gacc[j][0], gacc[j][1]);
            *(float2*)&Gb[li1 * 68 + c] = make_float2(gacc[j][2], gacc[j][3]);
        }
    }
    __syncthreads();   // P3: G chunk0 done; FRB free for iter 0

    float oacc[4][4] = {};
    float m0r = -CUDART_INF_F, m1r = -CUDART_INF_F;
    float l0 = 0.0f, l1 = 0.0f;

    for (int t = 0; t < 32; t++) {
        // loads (no leading barrier: FRK/FRB last read 2 barriers ago; V double-buffered)
        ld_split_i(kb + (size_t)t * 64 * QKVW, sm + FRK, tid);
        ld_v(vb + (size_t)t * 64 * QKVW, sm + FVS + (t & 1) * VSLOT, tid);
        ld_split_i(g_relk + (size_t)(relbase + 64 * (t + 1)) * QKVW + h * 64,
                   sm + FRB, tid);
        __syncthreads();   // S2: loads visible

        // cb (from K) and db[(t+1)&1] (from band)
        {
            int col = tid >> 2;
            float accc = 0.0f, accd = 0.0f;
            #pragma unroll
            for (int dd = 0; dd < 16; dd++) {
                int d = (tid & 3) + 4 * dd;
                int off = dd * GI + POS8(col) + 2 * (tid & 3);
                float2 kv = *(float2*)&sm[FRK + off];
                float2 bv = *(float2*)&sm[FRB + off];
                float w1 = rcb[h * 64 + d], w2 = rpb[h * 64 + d];
                accc = fmaf(w1, kv.x + kv.y, accc);
                accd = fmaf(w2, bv.x + bv.y, accd);
            }
            accc += __shfl_xor_sync(0xFFFFFFFFu, accc, 1);
            accc += __shfl_xor_sync(0xFFFFFFFFu, accc, 2);
            accd += __shfl_xor_sync(0xFFFFFFFFu, accd, 1);
            accd += __shfl_xor_sync(0xFFFFFFFFu, accd, 2);
            if ((tid & 3) == 0) {
                sm[FCB + col] = accc;
                sm[FDB + ((t + 1) & 1) * 64 + col] = accd;
            }
        }

        // content mma: cacc = Q x K
        float cacc[4][4] = {};
        #pragma unroll
        for (int kkg = 0; kkg < 8; kkg++) {
            int g0 = (2 * kkg) * GI, g1 = g0 + GI;
            #pragma unroll
            for (int j = 0; j < 4; j++) {
                int nb = POS8(nwl + 8 * j + g) + 2 * tig;
                float2 b0 = *(float2*)&sm[FRK + g0 + nb];
                float2 b1 = *(float2*)&sm[FRK + g1 + nb];
                uint32_t bh2[2] = { FU(b0.x), FU(b1.x) };
                uint32_t bl2[2] = { FU(b0.y), FU(b1.y) };
                mma8x3(cacc[j], qh[kkg], ql[kkg], bh2, bl2);
            }
        }

        // G mma chunk t+1 -> Gbuf slot (t+1)&1
        {
            float gacc[4][4] = {};
            #pragma unroll
            for (int kkg = 0; kkg < 8; kkg++) {
                int g0 = (2 * kkg) * GI, g1 = g0 + GI;
                #pragma unroll
                for (int j = 0; j < 4; j++) {
                    int nb = POS8(nwl + 8 * j + g) + 2 * tig;
                    float2 b0 = *(float2*)&sm[FRB + g0 + nb];
                    float2 b1 = *(float2*)&sm[FRB + g1 + nb];
                    uint32_t bh2[2] = { FU(b0.x), FU(b1.x) };
                    uint32_t bl2[2] = { FU(b0.y), FU(b1.y) };
                    mma8x3(gacc[j], qh[kkg], ql[kkg], bh2, bl2);
                }
            }
            float* Gb = sm + FGB + ((t + 1) & 1) * GSLOT2;
            #pragma unroll
            for (int j = 0; j < 4; j++) {
                int c = nwl + 8 * j + 2 * tig;
                *(float2*)&Gb[li0 * 68 + c] = make_float2(gacc[j][0], gacc[j][1]);
                *(float2*)&Gb[li1 * 68 + c] = make_float2(gacc[j][2], gacc[j][3]);
            }
        }
        __syncthreads();   // S3: Gbuf + cb + db visible

        // gather + biases + rowmax
        const float* G0 = sm + FGB + (t & 1) * GSLOT2;
        const float* G1 = sm + FGB + ((t + 1) & 1) * GSLOT2;
        const float* db0 = sm + FDB + (t & 1) * 64;
        const float* db1 = sm + FDB + ((t + 1) & 1) * 64;
        float s0[8], s1[8];
        float rm0 = -CUDART_INF_F, rm1 = -CUDART_INF_F;
        #pragma unroll
        for (int j = 0; j < 4; j++) {
            #pragma unroll
            for (int e = 0; e < 2; e++) {
                int lj = nwl + 8 * j + 2 * tig + e;
                float cbv = sm[FCB + lj];
                int rl0 = lj - li0 + 63;
                int rl1 = lj - li1 + 63;
                float gv0 = (rl0 < 64) ? (G0[li0 * 68 + rl0] + db0[rl0])
                                       : (G1[li0 * 68 + rl0 - 64] + db1[rl0 - 64]);
                float gv1 = (rl1 < 64) ? (G0[li1 * 68 + rl1] + db0[rl1])
                                       : (G1[li1 * 68 + rl1 - 64] + db1[rl1 - 64]);
                float v0 = cacc[j][e]     + gv0 + cbv;
                float v1 = cacc[j][2 + e] + gv1 + cbv;
                s0[2 * j + e] = v0; s1[2 * j + e] = v1;
                rm0 = fmaxf(rm0, v0); rm1 = fmaxf(rm1, v1);
            }
        }
        rm0 = fmaxf(rm0, __shfl_xor_sync(0xFFFFFFFFu, rm0, 1));
        rm0 = fmaxf(rm0, __shfl_xor_sync(0xFFFFFFFFu, rm0, 2));
        rm1 = fmaxf(rm1, __shfl_xor_sync(0xFFFFFFFFu, rm1, 1));
        rm1 = fmaxf(rm1, __shfl_xor_sync(0xFFFFFFFFu, rm1, 2));
        if (tig == 0) {
            sm[FREDM + (warp & 1) * 64 + li0] = rm0;
            sm[FREDM + (warp & 1) * 64 + li1] = rm1;
        }
        __syncthreads();   // S4: redm visible

        float mn0 = fmaxf(m0r, fmaxf(sm[FREDM + li0], sm[FREDM + 64 + li0]));
        float mn1 = fmaxf(m1r, fmaxf(sm[FREDM + li1], sm[FREDM + 64 + li1]));
        float sc0 = __expf(m0r - mn0), sc1 = __expf(m1r - mn1);
        m0r = mn0; m1r = mn1;
        float rs0 = 0.0f, rs1 = 0.0f;
        #pragma unroll
        for (int j = 0; j < 4; j++) {
            oacc[j][0] *= sc0; oacc[j][1] *= sc0;
            oacc[j][2] *= sc1; oacc[j][3] *= sc1;
            float p0a = __expf(s0[2 * j] - mn0), p0b = __expf(s0[2 * j + 1] - mn0);
            float p1a = __expf(s1[2 * j] - mn1), p1b = __expf(s1[2 * j + 1] - mn1);
            rs0 += p0a + p0b; rs1 += p1a + p1b;
            int c = nwl + 8 * j + 2 * tig;
            int pb = FPP + (c >> 2) * 260 + (c & 3);
            *(float2*)&sm[pb + 4 * li0] = make_float2(tfv(p0a), tfv(p0b));
            *(float2*)&sm[pb + 4 * li1] = make_float2(tfv(p1a), tfv(p1b));
        }
        rs0 += __shfl_xor_sync(0xFFFFFFFFu, rs0, 1);
        rs0 += __shfl_xor_sync(0xFFFFFFFFu, rs0, 2);
        rs1 += __shfl_xor_sync(0xFFFFFFFFu, rs1, 1);
        rs1 += __shfl_xor_sync(0xFFFFFFFFu, rs1, 2);
        if (tig == 0) {
            sm[FREDS + (warp & 1) * 64 + li0] = rs0;
            sm[FREDS + (warp & 1) * 64 + li1] = rs1;
        }
        __syncthreads();   // S5: P + reds visible

        l0 = l0 * sc0 + sm[FREDS + li0] + sm[FREDS + 64 + li0];
        l1 = l1 * sc1 + sm[FREDS + li1] + sm[FREDS + 64 + li1];

        // PV mma: oacc += P x V  (P hi-only x1, V rna)
        const float* Vt = sm + FVS + (t & 1) * VSLOT;
        #pragma unroll
        for (int kkg = 0; kkg < 8; kkg++) {
            uint32_t ph[4];
            ph[0] = FU(sm[FPP + 2 * kkg * 260 + 4 * li0 + tig]);
            ph[1] = FU(sm[FPP + 2 * kkg * 260 + 4 * li1 + tig]);
            ph[2] = FU(sm[FPP + (2 * kkg + 1) * 260 + 4 * li0 + tig]);
            ph[3] = FU(sm[FPP + (2 * kkg + 1) * 260 + 4 * li1 + tig]);
            #pragma unroll
            for (int j = 0; j < 4; j++) {
                int n = nwl + 8 * j + g;
                uint32_t bf[2] = { FU(Vt[2 * kkg * 260 + 4 * n + tig]),
                                   FU(Vt[(2 * kkg + 1) * 260 + 4 * n + tig]) };
                mma8(oacc[j], ph, bf);
            }
        }
    }

    float inv0 = 1.0f / l0, inv1 = 1.0f / l1;
    float* ob = g_o + (size_t)(b * NN + i0) * QKVW + h * 64;
    #pragma unroll
    for (int j = 0; j < 4; j++) {
        int c = nwl + 8 * j + 2 * tig;
        *(float2*)(ob + (size_t)li0 * QKVW + c) =
            make_float2(oacc[j][0] * inv0, oacc[j][1] * inv0);
        *(float2*)(ob + (size_t)li1 * QKVW + c) =
            make_float2(oacc[j][2] * inv1, oacc[j][3] * inv1);
    }
}

// ---------------- launch ----------------------------------------------------
static float* sym_addr(const void* sym) {
    void* p = nullptr;
    cudaGetSymbolAddress(&p, sym);
    return (float*)p;
}

extern "C" void kernel_launch(void* const* d_in, const int* in_sizes, int n_in,
                              void* d_out, int out_size) {
    const float* x    = (const float*)d_in[0];
    const float* Wq   = (const float*)d_in[1];
    const float* Wk   = (const float*)d_in[2];
    const float* Wv   = (const float*)d_in[3];
    const float* Wrel = (const float*)d_in[4];
    const float* Wout = (const float*)d_in[5];
    const float* bout = (const float*)d_in[6];
    const float* rcb  = (const float*)d_in[7];
    const float* rpb  = (const float*)d_in[8];
    float* out = (float*)d_out;

    float* p_pos  = sym_addr(g_pos);
    float* p_relk = sym_addr(g_relk);
    float* p_q    = sym_addr(g_q);
    float* p_k    = sym_addr(g_k);
    float* p_v    = sym_addr(g_v);
    float* p_o    = sym_addr(g_o);

    cudaFuncSetAttribute(gemm_tf32, cudaFuncAttributeMaxDynamicSharedMemorySize,
                         GEMM_SMEM);
    const int FUSED_SMEM = FSM_TOT * 4;   // 156,416 B
    cudaFuncSetAttribute(attn_fused, cudaFuncAttributeMaxDynamicSharedMemorySize,
                         FUSED_SMEM);

    // 1. positional embedding
    pos_embed_kernel<<<LREL, 32>>>();

    // 2. rel_k = pos @ Wrel  (row 4095 of g_relk stays 0 = pad)
    gemm_tf32<<<dim3(QKVW / 64, 32, 1), 256, GEMM_SMEM>>>(
        p_pos, Wrel, nullptr, nullptr, nullptr, p_relk, nullptr, nullptr,
        LREL, FF, QKVW, FF, QKVW, QKVW);

    // 3. q,k,v projections fused into one launch
    gemm_tf32<<<dim3(QKVW / 64, (BB * NN) / 128, 3), 256, GEMM_SMEM>>>(
        x, Wq, Wk, Wv, nullptr, p_q, p_k, p_v,
        BB * NN, DIMX, QKVW, DIMX, QKVW, QKVW);

    // 4. fused logits + online softmax + P@V  (256 threads)
    attn_fused<<<dim3(NN / 64, BB * HH), 256, FUSED_SMEM>>>(rcb, rpb);

    // 5. out = O @ Wout + b_out
    gemm_tf32<<<dim3(DIMX / 64, (BB * NN) / 128, 1), 256, GEMM_SMEM>>>(
        p_o, Wout, nullptr, nullptr, bout, out, nullptr, nullptr,
        BB * NN, QKVW, DIMX, QKVW, DIMX, DIMX);
}

// round 15
// speedup vs baseline: 1.6143x; 1.5312x over previous
#include <cuda_runtime.h>
#include <math.h>
#include <math_constants.h>
#include <stdint.h>

// Problem constants
#define BB 2
#define NN 2048
#define DIMX 768
#define HH 8
#define FF 192
#define LREL 4095            // 2*N - 1
#define QKVW 512             // H * DK

// ---------------- scratch (device globals; no allocation allowed) ----------
__device__ __align__(256) float g_pos[(size_t)LREL * FF];
__device__ __align__(256) float g_relk[(size_t)(LREL + 1) * QKVW]; // +1 pad row (stays 0)
__device__ __align__(256) float g_q[(size_t)BB * NN * QKVW];       // [b][n][h*64+d]
__device__ __align__(256) float g_k[(size_t)BB * NN * QKVW];
__device__ __align__(256) float g_v[(size_t)BB * NN * QKVW];
__device__ __align__(256) float g_o[(size_t)BB * NN * QKVW];

// ---------------- tf32 mma helpers -----------------------------------------
__device__ __forceinline__ uint32_t f2tf(float x) {
    uint32_t r; asm("cvt.rna.tf32.f32 %0, %1;" : "=r"(r) : "f"(x));
    return r;
}
__device__ __forceinline__ float tfv(float x) { return __uint_as_float(f2tf(x)); }
__device__ __forceinline__ void mma8(float* d, const uint32_t* a, const uint32_t* b) {
    asm volatile(
        "mma.sync.aligned.m16n8k8.row.col.f32.tf32.tf32.f32 "
        "{%0,%1,%2,%3},{%4,%5,%6,%7},{%8,%9},{%0,%1,%2,%3};\n"
        : "+f"(d[0]), "+f"(d[1]), "+f"(d[2]), "+f"(d[3])
        : "r"(a[0]), "r"(a[1]), "r"(a[2]), "r"(a[3]), "r"(b[0]), "r"(b[1]));
}
__device__ __forceinline__ void mma8x3(float* d, const uint32_t* ahi, const uint32_t* alo,
                                       const uint32_t* bhi, const uint32_t* blo) {
    mma8(d, ahi, blo);
    mma8(d, alo, bhi);
    mma8(d, ahi, bhi);
}
#define FU(x) __float_as_uint(x)

// ---------------- K1: positional embedding ----------------------------------
__global__ void pos_embed_kernel() {
    int row = blockIdx.x;
    int i = threadIdx.x;
    float dist = (float)(row - (NN - 1));
    float ad = fabsf(dist);

    float half_life = exp2f(3.0f + 8.0f * (float)i / 31.0f);
    float f_exp = exp2f(-ad / half_life);

    float width = exp2f((float)(i + 1)) - 1.0f;
    float f_cm = (width > ad) ? 1.0f : 0.0f;

    float mean = 64.0f * (float)(i + 1);
    float conc = (mean / 32.0f) * (mean / 32.0f);
    float rate = mean / 1024.0f;
    float log_unnorm = (conc - 1.0f) * logf(ad) - rate * ad;
    float log_norm = lgammaf(conc) - conc * logf(rate);
    float prob = expf(log_unnorm - log_norm) + 1e-8f;
    float pmax = prob;
    #pragma unroll
    for (int o = 16; o; o >>= 1) pmax = fmaxf(pmax, __shfl_xor_sync(0xFFFFFFFFu, pmax, o));
    float f_g = prob / pmax;

    float sgn = (dist > 0.0f) ? 1.0f : ((dist < 0.0f) ? -1.0f : 0.0f);

    float* out = g_pos + (size_t)row * FF;
    out[i]       = f_exp;
    out[32 + i]  = f_cm;
    out[64 + i]  = f_g;
    out[96 + i]  = sgn * f_exp;
    out[128 + i] = sgn * f_cm;
    out[160 + i] = sgn * f_g;
}

// ---------------- K2: tf32x3 GEMM v2 (unchanged) ----------------------------
#define GA 516
#define GB 260
#define VAH 0
#define VAL 4128
#define VBH 8256
#define VBL 10336
#define GEMM_SMEM ((10336 + 2080) * 4)
__global__ __launch_bounds__(256) void gemm_tf32(
    const float* __restrict__ A, const float* __restrict__ B0,
    const float* __restrict__ B1, const float* __restrict__ B2,
    const float* __restrict__ bias, float* __restrict__ C0,
    float* __restrict__ C1, float* __restrict__ C2,
    int M, int K, int Nc, int lda, int ldb, int ldc) {
    extern __shared__ float sg[];
    float* sAh = sg + VAH; float* sAl = sg + VAL;
    float* sBh = sg + VBH; float* sBl = sg + VBL;

    const float* B = B0;
    float* C = C0;
    if (blockIdx.z == 1) { B = B1; C = C1; }
    else if (blockIdx.z == 2) { B = B2; C = C2; }

    int tid = threadIdx.x;
    int warp = tid >> 5, lane = tid & 31;
    int g = lane >> 2, tig = lane & 3;
    int mw = (warp >> 1) * 32, nw = (warp & 1) * 32;
    int m0 = blockIdx.y * 128, n0 = blockIdx.x * 64;

    float acc[2][4][4] = {};

    int am = tid & 127, akg0 = tid >> 7;
    int bn = tid & 63,  bkg0 = tid >> 6;

    for (int k0 = 0; k0 < K; k0 += 32) {
        #pragma unroll
        for (int r = 0; r < 4; r++) {
            int kg = akg0 + 2 * r;
            int m = m0 + am;
            float4 v = make_float4(0.f, 0.f, 0.f, 0.f);
            if (m < M) v = *(const float4*)(A + (size_t)m * lda + k0 + kg * 4);
            float h0 = tfv(v.x), h1 = tfv(v.y), h2 = tfv(v.z), h3 = tfv(v.w);
            *(float4*)&sAh[kg * GA + am * 4] = make_float4(h0, h1, h2, h3);
            *(float4*)&sAl[kg * GA + am * 4] =
                make_float4(v.x - h0, v.y - h1, v.z - h2, v.w - h3);
        }
        #pragma unroll
        for (int r = 0; r < 2; r++) {
            int kg = bkg0 + 4 * r;
            const float* bp = B + (size_t)(k0 + kg * 4) * ldb + n0 + bn;
            float x0 = bp[0];
            float x1 = bp[(size_t)ldb];
            float x2 = bp[2 * (size_t)ldb];
            float x3 = bp[3 * (size_t)ldb];
            float h0 = tfv(x0), h1 = tfv(x1), h2 = tfv(x2), h3 = tfv(x3);
            *(float4*)&sBh[kg * GB + bn * 4] = make_float4(h0, h1, h2, h3);
            *(float4*)&sBl[kg * GB + bn * 4] =
                make_float4(x0 - h0, x1 - h1, x2 - h2, x3 - h3);
        }
        __syncthreads();
        #pragma unroll
        for (int kk = 0; kk < 32; kk += 8) {
            int qa = (kk >> 2) * GA, qb2 = (kk >> 2) * GB;
            uint32_t ah[2][4], al[2][4], bhf[4][2], blf[4][2];
            #pragma unroll
            for (int f = 0; f < 2; f++) {
                int ma = (mw + 16 * f + g) * 4 + tig;
                ah[f][0] = FU(sAh[qa + ma]);
                ah[f][1] = FU(sAh[qa + ma + 32]);
                ah[f][2] = FU(sAh[qa + GA + ma]);
                ah[f][3] = FU(sAh[qa + GA + ma + 32]);
                al[f][0] = FU(sAl[qa + ma]);
                al[f][1] = FU(sAl[qa + ma + 32]);
                al[f][2] = FU(sAl[qa + GA + ma]);
                al[f][3] = FU(sAl[qa + GA + ma + 32]);
            }
            #pragma unroll
            for (int j = 0; j < 4; j++) {
                int nb = (nw + 8 * j + g) * 4 + tig;
                bhf[j][0] = FU(sBh[qb2 + nb]);
                bhf[j][1] = FU(sBh[qb2 + GB + nb]);
                blf[j][0] = FU(sBl[qb2 + nb]);
                blf[j][1] = FU(sBl[qb2 + GB + nb]);
            }
            #pragma unroll
            for (int f = 0; f < 2; f++)
                #pragma unroll
                for (int j = 0; j < 4; j++) mma8(acc[f][j], ah[f], bhf[j]);
            #pragma unroll
            for (int f = 0; f < 2; f++)
                #pragma unroll
                for (int j = 0; j < 4; j++) mma8(acc[f][j], ah[f], blf[j]);
            #pragma unroll
            for (int f = 0; f < 2; f++)
                #pragma unroll
                for (int j = 0; j < 4; j++) mma8(acc[f][j], al[f], bhf[j]);
        }
        __syncthreads();
    }

    #pragma unroll
    for (int f = 0; f < 2; f++) {
        #pragma unroll
        for (int j = 0; j < 4; j++) {
            int n = n0 + nw + 8 * j + 2 * tig;
            float b0v = bias ? bias[n] : 0.0f;
            float b1v = bias ? bias[n + 1] : 0.0f;
            int m = m0 + mw + 16 * f + g;
            if (m < M)
                *(float2*)(C + (size_t)m * ldc + n) =
                    make_float2(acc[f][j][0] + b0v, acc[f][j][1] + b1v);
            if (m + 8 < M)
                *(float2*)(C + (size_t)(m + 8) * ldc + n) =
                    make_float2(acc[f][j][2] + b0v, acc[f][j][3] + b1v);
        }
    }
}

// ---------------- K3: fused attention (R12 base; PV x1 + __expf only) -------
// Interleaved hi/lo layout for K/band: (k>>2)*GI + POS8(n) + 2*(k&3) (+1 lo)
#define GI 546
#define POS8(n) (8 * (n) + 2 * ((n) >> 2))
#define FRK 0                      // K tile   16*546 = 8736
#define FRB 8736                   // band tile 8736
#define FPS 17472                  // P tile (also Qraw temp) 8736
#define FVS 26208                  // V tile 16*260 = 4160
#define FGB 30368                  // G buf 2 slots x 4352
#define FCB 39072                  // cb[64]
#define FDB 39136                  // db[2][64]
#define FREDM 39264                // 128
#define FREDS 39392                // 128
#define FSM_TOT 39520              // *4 = 158,080 B
#define GSLOT2 4352

// split-load 64x64 tile (row-major, ld=QKVW) into interleaved hi/lo, 256 thr
__device__ __forceinline__ void ld_split_i(const float* src, float* dst, int tid) {
    int n = tid & 63, dg = tid >> 6;
    #pragma unroll
    for (int r = 0; r < 4; r++) {
        int grp = dg + 4 * r;
        float4 v = *(const float4*)(src + (size_t)n * QKVW + grp * 4);
        float h0 = tfv(v.x), h1 = tfv(v.y), h2 = tfv(v.z), h3 = tfv(v.w);
        int base = grp * GI + POS8(n);
        *(float2*)&dst[base + 0] = make_float2(h0, v.x - h0);
        *(float2*)&dst[base + 2] = make_float2(h1, v.y - h1);
        *(float2*)&dst[base + 4] = make_float2(h2, v.z - h2);
        *(float2*)&dst[base + 6] = make_float2(h3, v.w - h3);
    }
}
// V loader: k4 B-operand layout (k = seq row, n = dv), rna-rounded
__device__ __forceinline__ void ld_v(const float* src, float* dv, int tid) {
    int row = tid & 63, dg = tid >> 6;
    #pragma unroll
    for (int r = 0; r < 4; r++) {
        int grp = dg + 4 * r;
        float4 v = *(const float4*)(src + (size_t)row * QKVW + grp * 4);
        int bb = (row >> 2) * 260 + (row & 3);
        dv[bb + (grp * 4 + 0) * 4] = tfv(v.x);
        dv[bb + (grp * 4 + 1) * 4] = tfv(v.y);
        dv[bb + (grp * 4 + 2) * 4] = tfv(v.z);
        dv[bb + (grp * 4 + 3) * 4] = tfv(v.w);
    }
}

__global__ __launch_bounds__(256, 1) void attn_fused(const float* __restrict__ rcb,
                                                     const float* __restrict__ rpb) {
    extern __shared__ float sm[];

    int bhid = blockIdx.y;
    int b = bhid >> 3, h = bhid & 7;
    int i0 = blockIdx.x * 64;
    int tid = threadIdx.x, warp = tid >> 5, lane = tid & 31;
    int g = lane >> 2, tig = lane & 3;
    int mwl = (warp >> 1) * 16, nwl = (warp & 1) * 32;
    int li0 = mwl + g, li1 = li0 + 8;

    const float* qb = g_q + (size_t)b * NN * QKVW + h * 64;
    const float* kb = g_k + (size_t)b * NN * QKVW + h * 64;
    const float* vb = g_v + (size_t)b * NN * QKVW + h * 64;
    int relbase = 1984 - i0;

    // ---- prologue: Qraw (scaled) -> FPS temp; band chunk0 -> FRB ----
    {
        int row = tid & 63, dg = tid >> 6;
        #pragma unroll
        for (int r = 0; r < 4; r++) {
            int grp = dg + 4 * r;
            float4 v = *(const float4*)(qb + (size_t)(i0 + row) * QKVW + grp * 4);
            *(float4*)&sm[FPS + row * 68 + grp * 4] =
                make_float4(v.x * 0.125f, v.y * 0.125f, v.z * 0.125f, v.w * 0.125f);
        }
    }
    ld_split_i(g_relk + (size_t)relbase * QKVW + h * 64, sm + FRB, tid);
    __syncthreads();

    // extract Q fragments to registers (hi/lo)
    uint32_t qh[8][4], ql[8][4];
    #pragma unroll
    for (int kkg = 0; kkg < 8; kkg++) {
        int kk = 8 * kkg;
        float a0 = sm[FPS + li0 * 68 + kk + tig];
        float a1 = sm[FPS + li1 * 68 + kk + tig];
        float a2 = sm[FPS + li0 * 68 + kk + tig + 4];
        float a3 = sm[FPS + li1 * 68 + kk + tig + 4];
        float h0 = tfv(a0), h1 = tfv(a1), h2 = tfv(a2), h3 = tfv(a3);
        qh[kkg][0] = FU(h0); qh[kkg][1] = FU(h1); qh[kkg][2] = FU(h2); qh[kkg][3] = FU(h3);
        ql[kkg][0] = FU(tfv(a0 - h0)); ql[kkg][1] = FU(tfv(a1 - h1));
        ql[kkg][2] = FU(tfv(a2 - h2)); ql[kkg][3] = FU(tfv(a3 - h3));
    }

    // db[0] from band chunk0
    {
        int col = tid >> 2;
        float accd = 0.0f;
        #pragma unroll
        for (int dd = 0; dd < 16; dd++) {
            int d = (tid & 3) + 4 * dd;
            float2 bv = *(float2*)&sm[FRB + dd * GI + POS8(col) + 2 * (tid & 3)];
            accd = fmaf(rpb[h * 64 + d], bv.x + bv.y, accd);
        }
        accd += __shfl_xor_sync(0xFFFFFFFFu, accd, 1);
        accd += __shfl_xor_sync(0xFFFFFFFFu, accd, 2);
        if ((tid & 3) == 0) sm[FDB + col] = accd;
    }

    // G chunk0 -> Gbuf slot 0
    {
        float gacc[4][4] = {};
        #pragma unroll
        for (int kkg = 0; kkg < 8; kkg++) {
            int g0 = (2 * kkg) * GI, g1 = g0 + GI;
            #pragma unroll
            for (int j = 0; j < 4; j++) {
                int nb = POS8(nwl + 8 * j + g) + 2 * tig;
                float2 b0 = *(float2*)&sm[FRB + g0 + nb];
                float2 b1 = *(float2*)&sm[FRB + g1 + nb];
                uint32_t bh2[2] = { FU(b0.x), FU(b1.x) };
                uint32_t bl2[2] = { FU(b0.y), FU(b1.y) };
                mma8x3(gacc[j], qh[kkg], ql[kkg], bh2, bl2);
            }
        }
        float* Gb = sm + FGB;
        #pragma unroll
        for (int j = 0; j < 4; j++) {
            int c = nwl + 8 * j + 2 * tig;
            *(float2*)&Gb[li0 * 68 + c] = make_float2(gacc[j][0], gacc[j][1]);
            *(float2*)&Gb[li1 * 68 + c] = make_float2(gacc[j][2], gacc[j][3]);
        }
    }

    float oacc[4][4] = {};
    float m0r = -CUDART_INF_F, m1r = -CUDART_INF_F;
    float l0 = 0.0f, l1 = 0.0f;

    for (int t = 0; t < 32; t++) {
        __syncthreads();   // S1
        ld_split_i(kb + (size_t)t * 64 * QKVW, sm + FRK, tid);
        ld_v(vb + (size_t)t * 64 * QKVW, sm + FVS, tid);
        ld_split_i(g_relk + (size_t)(relbase + 64 * (t + 1)) * QKVW + h * 64,
                   sm + FRB, tid);
        __syncthreads();   // S2

        // cb (from K) and db[(t+1)&1] (from band)
        {
            int col = tid >> 2;
            float accc = 0.0f, accd = 0.0f;
            #pragma unroll
            for (int dd = 0; dd < 16; dd++) {
                int d = (tid & 3) + 4 * dd;
                int off = dd * GI + POS8(col) + 2 * (tid & 3);
                float2 kv = *(float2*)&sm[FRK + off];
                float2 bv = *(float2*)&sm[FRB + off];
                float w1 = rcb[h * 64 + d], w2 = rpb[h * 64 + d];
                accc = fmaf(w1, kv.x + kv.y, accc);
                accd = fmaf(w2, bv.x + bv.y, accd);
            }
            accc += __shfl_xor_sync(0xFFFFFFFFu, accc, 1);
            accc += __shfl_xor_sync(0xFFFFFFFFu, accc, 2);
            accd += __shfl_xor_sync(0xFFFFFFFFu, accd, 1);
            accd += __shfl_xor_sync(0xFFFFFFFFu, accd, 2);
            if ((tid & 3) == 0) {
                sm[FCB + col] = accc;
                sm[FDB + ((t + 1) & 1) * 64 + col] = accd;
            }
        }

        // content mma: cacc = Q x K
        float cacc[4][4] = {};
        #pragma unroll
        for (int kkg = 0; kkg < 8; kkg++) {
            int g0 = (2 * kkg) * GI, g1 = g0 + GI;
            #pragma unroll
            for (int j = 0; j < 4; j++) {
                int nb = POS8(nwl + 8 * j + g) + 2 * tig;
                float2 b0 = *(float2*)&sm[FRK + g0 + nb];
                float2 b1 = *(float2*)&sm[FRK + g1 + nb];
                uint32_t bh2[2] = { FU(b0.x), FU(b1.x) };
                uint32_t bl2[2] = { FU(b0.y), FU(b1.y) };
                mma8x3(cacc[j], qh[kkg], ql[kkg], bh2, bl2);
            }
        }

        // G mma chunk t+1 -> Gbuf slot (t+1)&1
        {
            float gacc[4][4] = {};
            #pragma unroll
            for (int kkg = 0; kkg < 8; kkg++) {
                int g0 = (2 * kkg) * GI, g1 = g0 + GI;
                #pragma unroll
                for (int j = 0; j < 4; j++) {
                    int nb = POS8(nwl + 8 * j + g) + 2 * tig;
                    float2 b0 = *(float2*)&sm[FRB + g0 + nb];
                    float2 b1 = *(float2*)&sm[FRB + g1 + nb];
                    uint32_t bh2[2] = { FU(b0.x), FU(b1.x) };
                    uint32_t bl2[2] = { FU(b0.y), FU(b1.y) };
                    mma8x3(gacc[j], qh[kkg], ql[kkg], bh2, bl2);
                }
            }
            float* Gb = sm + FGB + ((t + 1) & 1) * GSLOT2;
            #pragma unroll
            for (int j = 0; j < 4; j++) {
                int c = nwl + 8 * j + 2 * tig;
                *(float2*)&Gb[li0 * 68 + c] = make_float2(gacc[j][0], gacc[j][1]);
                *(float2*)&Gb[li1 * 68 + c] = make_float2(gacc[j][2], gacc[j][3]);
            }
        }
        __syncthreads();   // S3

        // gather + biases + rowmax
        const float* G0 = sm + FGB + (t & 1) * GSLOT2;
        const float* G1 = sm + FGB + ((t + 1) & 1) * GSLOT2;
        const float* db0 = sm + FDB + (t & 1) * 64;
        const float* db1 = sm + FDB + ((t + 1) & 1) * 64;
        float s0[8], s1[8];
        float rm0 = -CUDART_INF_F, rm1 = -CUDART_INF_F;
        #pragma unroll
        for (int j = 0; j < 4; j++) {
            #pragma unroll
            for (int e = 0; e < 2; e++) {
                int lj = nwl + 8 * j + 2 * tig + e;
                float cbv = sm[FCB + lj];
                int rl0 = lj - li0 + 63;
                int rl1 = lj - li1 + 63;
                float gv0 = (rl0 < 64) ? (G0[li0 * 68 + rl0] + db0[rl0])
                                       : (G1[li0 * 68 + rl0 - 64] + db1[rl0 - 64]);
                float gv1 = (rl1 < 64) ? (G0[li1 * 68 + rl1] + db0[rl1])
                                       : (G1[li1 * 68 + rl1 - 64] + db1[rl1 - 64]);
                float v0 = cacc[j][e]     + gv0 + cbv;
                float v1 = cacc[j][2 + e] + gv1 + cbv;
                s0[2 * j + e] = v0; s1[2 * j + e] = v1;
                rm0 = fmaxf(rm0, v0); rm1 = fmaxf(rm1, v1);
            }
        }
        rm0 = fmaxf(rm0, __shfl_xor_sync(0xFFFFFFFFu, rm0, 1));
        rm0 = fmaxf(rm0, __shfl_xor_sync(0xFFFFFFFFu, rm0, 2));
        rm1 = fmaxf(rm1, __shfl_xor_sync(0xFFFFFFFFu, rm1, 1));
        rm1 = fmaxf(rm1, __shfl_xor_sync(0xFFFFFFFFu, rm1, 2));
        if (tig == 0) {
            sm[FREDM + (warp & 1) * 64 + li0] = rm0;
            sm[FREDM + (warp & 1) * 64 + li1] = rm1;
        }
        __syncthreads();   // S4

        float mn0 = fmaxf(m0r, fmaxf(sm[FREDM + li0], sm[FREDM + 64 + li0]));
        float mn1 = fmaxf(m1r, fmaxf(sm[FREDM + li1], sm[FREDM + 64 + li1]));
        float sc0 = __expf(m0r - mn0), sc1 = __expf(m1r - mn1);
        m0r = mn0; m1r = mn1;
        float rs0 = 0.0f, rs1 = 0.0f;
        #pragma unroll
        for (int j = 0; j < 4; j++) {
            oacc[j][0] *= sc0; oacc[j][1] *= sc0;
            oacc[j][2] *= sc1; oacc[j][3] *= sc1;
            float p0a = __expf(s0[2 * j] - mn0), p0b = __expf(s0[2 * j + 1] - mn0);
            float p1a = __expf(s1[2 * j] - mn1), p1b = __expf(s1[2 * j + 1] - mn1);
            rs0 += p0a + p0b; rs1 += p1a + p1b;
            int c = nwl + 8 * j + 2 * tig;
            int pb = FPS + (c >> 2) * GI + 2 * (c & 3);
            sm[pb + POS8(li0)]     = tfv(p0a);
            sm[pb + POS8(li0) + 2] = tfv(p0b);
            sm[pb + POS8(li1)]     = tfv(p1a);
            sm[pb + POS8(li1) + 2] = tfv(p1b);
        }
        rs0 += __shfl_xor_sync(0xFFFFFFFFu, rs0, 1);
        rs0 += __shfl_xor_sync(0xFFFFFFFFu, rs0, 2);
        rs1 += __shfl_xor_sync(0xFFFFFFFFu, rs1, 1);
        rs1 += __shfl_xor_sync(0xFFFFFFFFu, rs1, 2);
        if (tig == 0) {
            sm[FREDS + (warp & 1) * 64 + li0] = rs0;
            sm[FREDS + (warp & 1) * 64 + li1] = rs1;
        }
        __syncthreads();   // S5

        l0 = l0 * sc0 + sm[FREDS + li0] + sm[FREDS + 64 + li0];
        l1 = l1 * sc1 + sm[FREDS + li1] + sm[FREDS + 64 + li1];

        // PV mma: oacc += P x V  (P hi-only x1, V rna)
        #pragma unroll
        for (int kkg = 0; kkg < 8; kkg++) {
            int pg0 = FPS + (2 * kkg) * GI, pg1 = pg0 + GI;
            uint32_t ph[4];
            ph[0] = FU(sm[pg0 + POS8(li0) + 2 * tig]);
            ph[1] = FU(sm[pg0 + POS8(li1) + 2 * tig]);
            ph[2] = FU(sm[pg1 + POS8(li0) + 2 * tig]);
            ph[3] = FU(sm[pg1 + POS8(li1) + 2 * tig]);
            #pragma unroll
            for (int j = 0; j < 4; j++) {
                int n = nwl + 8 * j + g;
                uint32_t bf[2] = { FU(sm[FVS + 2 * kkg * 260 + 4 * n + tig]),
                                   FU(sm[FVS + (2 * kkg + 1) * 260 + 4 * n + tig]) };
                mma8(oacc[j], ph, bf);
            }
        }
    }

    float inv0 = 1.0f / l0, inv1 = 1.0f / l1;
    float* ob = g_o + (size_t)(b * NN + i0) * QKVW + h * 64;
    #pragma unroll
    for (int j = 0; j < 4; j++) {
        int c = nwl + 8 * j + 2 * tig;
        *(float2*)(ob + (size_t)li0 * QKVW + c) =
            make_float2(oacc[j][0] * inv0, oacc[j][1] * inv0);
        *(float2*)(ob + (size_t)li1 * QKVW + c) =
            make_float2(oacc[j][2] * inv1, oacc[j][3] * inv1);
    }
}

// ---------------- launch ----------------------------------------------------
static float* sym_addr(const void* sym) {
    void* p = nullptr;
    cudaGetSymbolAddress(&p, sym);
    return (float*)p;
}

extern "C" void kernel_launch(void* const* d_in, const int* in_sizes, int n_in,
                              void* d_out, int out_size) {
    const float* x    = (const float*)d_in[0];
    const float* Wq   = (const float*)d_in[1];
    const float* Wk   = (const float*)d_in[2];
    const float* Wv   = (const float*)d_in[3];
    const float* Wrel = (const float*)d_in[4];
    const float* Wout = (const float*)d_in[5];
    const float* bout = (const float*)d_in[6];
    const float* rcb  = (const float*)d_in[7];
    const float* rpb  = (const float*)d_in[8];
    float* out = (float*)d_out;

    float* p_pos  = sym_addr(g_pos);
    float* p_relk = sym_addr(g_relk);
    float* p_q    = sym_addr(g_q);
    float* p_k    = sym_addr(g_k);
    float* p_v    = sym_addr(g_v);
    float* p_o    = sym_addr(g_o);

    cudaFuncSetAttribute(gemm_tf32, cudaFuncAttributeMaxDynamicSharedMemorySize,
                         GEMM_SMEM);
    const int FUSED_SMEM = FSM_TOT * 4;   // 158,080 B
    cudaFuncSetAttribute(attn_fused, cudaFuncAttributeMaxDynamicSharedMemorySize,
                         FUSED_SMEM);

    // 1. positional embedding
    pos_embed_kernel<<<LREL, 32>>>();

    // 2. rel_k = pos @ Wrel  (row 4095 of g_relk stays 0 = pad)
    gemm_tf32<<<dim3(QKVW / 64, 32, 1), 256, GEMM_SMEM>>>(
        p_pos, Wrel, nullptr, nullptr, nullptr, p_relk, nullptr, nullptr,
        LREL, FF, QKVW, FF, QKVW, QKVW);

    // 3. q,k,v projections fused into one launch
    gemm_tf32<<<dim3(QKVW / 64, (BB * NN) / 128, 3), 256, GEMM_SMEM>>>(
        x, Wq, Wk, Wv, nullptr, p_q, p_k, p_v,
        BB * NN, DIMX, QKVW, DIMX, QKVW, QKVW);

    // 4. fused logits + online softmax + P@V  (256 threads)
    attn_fused<<<dim3(NN / 64, BB * HH), 256, FUSED_SMEM>>>(rcb, rpb);

    // 5. out = O @ Wout + b_out
    gemm_tf32<<<dim3(DIMX / 64, (BB * NN) / 128, 1), 256, GEMM_SMEM>>>(
        p_o, Wout, nullptr, nullptr, bout, out, nullptr, nullptr,
        BB * NN, QKVW, DIMX, QKVW, DIMX, DIMX);
}